// round 13
// baseline (speedup 1.0000x reference)
#include <cuda_runtime.h>
#include <cuda_fp16.h>
#include <cstdint>

// ---------------- problem constants ----------------
#define MM      16
#define NN      8192
#define KK      8192
#define GS      128
#define KSPLIT  16
#define KRANGE  (KK / KSPLIT)        // 512 k per CTA
#define KBLKS   (KRANGE / 16)        // 32 k16-blocks
#define NGRP    (KRANGE / GS)        // 4 scale groups per CTA
#define TPB     128                  // 4 warps
#define WCOLS   32                   // columns per warp (4 n-tiles of 8)
#define CTACOLS 128
#define NCTA_N  (NN / CTACOLS)       // 64  -> grid = 64 x 16 = 1024 CTAs
#define XS_STRIDE 520                // halves; word-bank (4g+c)%32 distinct

// 16 * 16 * 8192 f32 = 8 MiB K-split partials
__device__ float g_part[(size_t)KSPLIT * MM * NN];
// per-ntile arrival counters (zero-initialized; last arriver resets to 0,
// so state is correct for every graph replay)
__device__ int g_cnt[NCTA_N];

// k-permuted dequant: ((w >> 4c) & 0x000F000F) | 0x64006400 gives fp16x2
// (1024+q[c], 1024+q[c+4]) in ONE LOP3 after the shift.  Slots (2c,2c+1)
// carry k=(c,c+4); x is staged into SMEM with the matching permutation.
static __device__ __forceinline__ __half2 dq4(uint32_t w, uint32_t sh4, __half2 s2) {
    uint32_t v;
    const uint32_t t = w >> sh4;
    asm("lop3.b32 %0, %1, 0x000F000F, 0x64006400, 0xEA;" : "=r"(v) : "r"(t));
    const uint32_t m1032 = 0xE408E408u;   // fp16x2 (-1032, -1032)
    __half2 h = __hadd2(*reinterpret_cast<__half2*>(&v),
                        *reinterpret_cast<const __half2*>(&m1032)); // (q-8) exact
    return __hmul2(h, s2);
}

static __device__ __forceinline__ void hmma16816(float* d, uint32_t a0, uint32_t a1,
                                                 uint32_t a2, uint32_t a3,
                                                 uint32_t b0, uint32_t b1) {
    asm volatile(
        "mma.sync.aligned.m16n8k16.row.col.f32.f16.f16.f32 "
        "{%0,%1,%2,%3}, {%4,%5,%6,%7}, {%8,%9}, {%0,%1,%2,%3};"
        : "+f"(d[0]), "+f"(d[1]), "+f"(d[2]), "+f"(d[3])
        : "r"(a0), "r"(a1), "r"(a2), "r"(a3), "r"(b0), "r"(b1));
}

// ---------------- fused: dequant + HMMA + last-CTA reduction ----------------
__global__ void __launch_bounds__(TPB, 6)
fp4hmma_fused(const float* __restrict__ x,       // [16, 8192] f32 (exact fp16 values)
              const int*   __restrict__ wp,      // [1024, 8192] int32 packed FP4
              const float* __restrict__ scales,  // [64, 8192] f32 (exact fp16 values)
              float* __restrict__ out)           // [16, 8192] f32 (half-rounded)
{
    __shared__ __align__(16) __half xs[MM][XS_STRIDE];
    __shared__ int is_last;

    const int tid  = threadIdx.x;
    const int wrp  = tid >> 5;        // 0..3
    const int lane = tid & 31;
    const int g    = lane >> 2;       // 0..7
    const int c    = lane & 3;        // 0..3
    const int kb0  = blockIdx.y * KRANGE;

    // ---- stage x slice [16 x 512] as fp16, k-PERMUTED per 8-k sub-block:
    // position 2j holds k=j, position 2j+1 holds k=j+4  (j = 0..3)
    #pragma unroll
    for (int it = 0; it < 8; ++it) {
        const int p  = tid + it * TPB;        // 8-float chunk id 0..1023
        const int m  = p >> 6;                // 64 chunks per row
        const int k8 = (p & 63) << 3;
        const float4 va = *(const float4*)&x[(size_t)m * KK + kb0 + k8];
        const float4 vb = *(const float4*)&x[(size_t)m * KK + kb0 + k8 + 4];
        *(__half2*)&xs[m][k8]     = __floats2half2_rn(va.x, vb.x);
        *(__half2*)&xs[m][k8 + 2] = __floats2half2_rn(va.y, vb.y);
        *(__half2*)&xs[m][k8 + 4] = __floats2half2_rn(va.z, vb.z);
        *(__half2*)&xs[m][k8 + 6] = __floats2half2_rn(va.w, vb.w);
    }
    __syncthreads();

    const int wb = blockIdx.x * CTACOLS + wrp * WCOLS;

    float acc[4][4];
    #pragma unroll
    for (int t = 0; t < 4; ++t)
        #pragma unroll
        for (int r = 0; r < 4; ++r) acc[t][r] = 0.0f;

    const uint32_t sh4   = (uint32_t)c * 4u;
    const int      prow0 = blockIdx.y * (KRANGE / 8);

    float snext[4];
    #pragma unroll
    for (int t = 0; t < 4; ++t)
        snext[t] = scales[(size_t)(blockIdx.y * NGRP) * NN + wb + t * 8 + g];
    __half2 s2[4];

    // weight double-buffer: wA/wB hold 8 words ({row0 t0..3, row1 t0..3})
    const int* wbase = &wp[(size_t)prow0 * NN + wb + g];
    uint32_t wA[8], wB[8];
    #pragma unroll
    for (int t = 0; t < 4; ++t) {
        wA[t]     = (uint32_t)wbase[t * 8];
        wA[4 + t] = (uint32_t)wbase[(size_t)NN + t * 8];
    }

    #pragma unroll 1
    for (int kb = 0; kb < KBLKS; kb += 2) {
        if ((kb & 7) == 0) {
            #pragma unroll
            for (int t = 0; t < 4; ++t)
                s2[t] = __half2half2(__float2half_rn(0.5f * snext[t]));
            const int gn = ((kb >> 3) + 1 < NGRP) ? (kb >> 3) + 1 : (kb >> 3);
            const size_t grow = (size_t)(blockIdx.y * NGRP + gn) * NN;
            #pragma unroll
            for (int t = 0; t < 4; ++t)
                snext[t] = scales[grow + wb + t * 8 + g];
        }

        // prefetch k-block kb+1 into wB
        {
            const int* p = wbase + (size_t)(kb + 1) * 2 * NN;
            #pragma unroll
            for (int t = 0; t < 4; ++t) {
                wB[t]     = (uint32_t)p[t * 8];
                wB[4 + t] = (uint32_t)p[(size_t)NN + t * 8];
            }
        }

        // consume wA (k-block kb)
        {
            const int klo = kb * 16 + c * 2;
            const uint32_t a0 = *(const uint32_t*)&xs[g][klo];
            const uint32_t a1 = *(const uint32_t*)&xs[g + 8][klo];
            const uint32_t a2 = *(const uint32_t*)&xs[g][klo + 8];
            const uint32_t a3 = *(const uint32_t*)&xs[g + 8][klo + 8];
            #pragma unroll
            for (int t = 0; t < 4; ++t) {
                const __half2 b0 = dq4(wA[t], sh4, s2[t]);
                const __half2 b1 = dq4(wA[4 + t], sh4, s2[t]);
                hmma16816(acc[t], a0, a1, a2, a3,
                          *(const uint32_t*)&b0, *(const uint32_t*)&b1);
            }
        }

        // prefetch k-block kb+2 into wA (clamped)
        {
            const int kbn = (kb + 2 < KBLKS) ? kb + 2 : kb;
            const int* p = wbase + (size_t)kbn * 2 * NN;
            #pragma unroll
            for (int t = 0; t < 4; ++t) {
                wA[t]     = (uint32_t)p[t * 8];
                wA[4 + t] = (uint32_t)p[(size_t)NN + t * 8];
            }
        }

        // consume wB (k-block kb+1)
        {
            const int klo = (kb + 1) * 16 + c * 2;
            const uint32_t a0 = *(const uint32_t*)&xs[g][klo];
            const uint32_t a1 = *(const uint32_t*)&xs[g + 8][klo];
            const uint32_t a2 = *(const uint32_t*)&xs[g][klo + 8];
            const uint32_t a3 = *(const uint32_t*)&xs[g + 8][klo + 8];
            #pragma unroll
            for (int t = 0; t < 4; ++t) {
                const __half2 b0 = dq4(wB[t], sh4, s2[t]);
                const __half2 b1 = dq4(wB[4 + t], sh4, s2[t]);
                hmma16816(acc[t], a0, a1, a2, a3,
                          *(const uint32_t*)&b0, *(const uint32_t*)&b1);
            }
        }
    }

    // ---- write K-split partials ----
    const size_t pbase = (size_t)blockIdx.y * MM * NN;
    #pragma unroll
    for (int t = 0; t < 4; ++t) {
        const int n = wb + t * 8 + c * 2;
        *(float2*)&g_part[pbase + (size_t)g * NN + n]       = make_float2(acc[t][0], acc[t][1]);
        *(float2*)&g_part[pbase + (size_t)(g + 8) * NN + n] = make_float2(acc[t][2], acc[t][3]);
    }

    // ---- signal: last CTA of this ntile reduces ----
    __threadfence();                       // partials visible device-wide
    __syncthreads();                       // all warps' fences done
    if (tid == 0) {
        const int old = atomicAdd(&g_cnt[blockIdx.x], 1);
        is_last = (old == KSPLIT - 1);
    }
    __syncthreads();

    if (is_last) {
        __threadfence();                   // acquire: order reads after the atomic
        const int n = blockIdx.x * CTACOLS + tid;   // 128 threads, 128 columns
        float v[MM];
        #pragma unroll
        for (int m = 0; m < MM; ++m) v[m] = 0.0f;
        #pragma unroll
        for (int s = 0; s < KSPLIT; ++s) {
            const float* p = &g_part[(size_t)s * MM * NN + n];
            #pragma unroll
            for (int m = 0; m < MM; ++m)       // 16 loads in flight, L2-hot
                v[m] += p[(size_t)m * NN];
        }
        #pragma unroll
        for (int m = 0; m < MM; ++m)
            out[(size_t)m * NN + n] = __half2float(__float2half(v[m]));
        if (tid == 0) g_cnt[blockIdx.x] = 0;   // reset for next replay
    }
}

extern "C" void kernel_launch(void* const* d_in, const int* in_sizes, int n_in,
                              void* d_out, int out_size)
{
    const float* x      = (const float*)d_in[0];
    const int*   wp     = (const int*)  d_in[1];
    const float* scales = (const float*)d_in[2];
    float*       out    = (float*)d_out;

    dim3 grid(NCTA_N, KSPLIT);
    fp4hmma_fused<<<grid, TPB>>>(x, wp, scales, out);
}

// round 14
// speedup vs baseline: 1.2771x; 1.2771x over previous
#include <cuda_runtime.h>
#include <cuda_fp16.h>
#include <cstdint>

// ---------------- problem constants ----------------
#define MM      16
#define NN      8192
#define KK      8192
#define GS      128
#define KSPLIT  16
#define KRANGE  (KK / KSPLIT)        // 512 k per CTA
#define KBLKS   (KRANGE / 16)        // 32 k16-blocks
#define NCHUNKS (KBLKS / 4)          // 8 cp.async chunks (4 k-blocks each)
#define NGRP    (KRANGE / GS)        // 4 scale groups per CTA
#define TPB     128                  // 4 warps
#define WCOLS   32                   // columns per warp (4 n-tiles of 8)
#define CTACOLS 128
#define NCTA_N  (NN / CTACOLS)       // 64  -> grid = 64 x 16 = 1024 CTAs
#define XS_STRIDE 520                // halves; word-bank (4g+c)%32 distinct

// 16 * 16 * 8192 f32 = 8 MiB K-split partials
__device__ float g_part[(size_t)KSPLIT * MM * NN];

// k-permuted dequant: ((w >> 4c) & 0x000F000F) | 0x64006400 gives fp16x2
// (1024+q[c], 1024+q[c+4]) in ONE LOP3 after the shift.
static __device__ __forceinline__ __half2 dq4(uint32_t w, uint32_t sh4, __half2 s2) {
    uint32_t v;
    const uint32_t t = w >> sh4;
    asm("lop3.b32 %0, %1, 0x000F000F, 0x64006400, 0xEA;" : "=r"(v) : "r"(t));
    const uint32_t m1032 = 0xE408E408u;   // fp16x2 (-1032, -1032)
    __half2 h = __hadd2(*reinterpret_cast<__half2*>(&v),
                        *reinterpret_cast<const __half2*>(&m1032)); // (q-8) exact
    return __hmul2(h, s2);
}

static __device__ __forceinline__ void hmma(float* d, uint32_t a0, uint32_t a1,
                                            uint32_t a2, uint32_t a3,
                                            uint32_t b0, uint32_t b1) {
    asm volatile(
        "mma.sync.aligned.m16n8k16.row.col.f32.f16.f16.f32 "
        "{%0,%1,%2,%3}, {%4,%5,%6,%7}, {%8,%9}, {%0,%1,%2,%3};"
        : "+f"(d[0]), "+f"(d[1]), "+f"(d[2]), "+f"(d[3])
        : "r"(a0), "r"(a1), "r"(a2), "r"(a3), "r"(b0), "r"(b1));
}

// ---------------- stage 1: cp.async-staged weights + HMMA ----------------
__global__ void __launch_bounds__(TPB, 6)
fp4hmma_stage1(const float* __restrict__ x,       // [16, 8192] f32 (exact fp16 values)
               const int*   __restrict__ wp,      // [1024, 8192] int32 packed FP4
               const float* __restrict__ scales)  // [64, 8192] f32 (exact fp16 values)
{
    __shared__ __align__(16) __half    xs[MM][XS_STRIDE];   // 16.25 KB
    __shared__ __align__(16) uint32_t  ws[4 * 1024];        // 16 KB: 4-buf weight ring

    const int tid  = threadIdx.x;
    const int wrp  = tid >> 5;        // 0..3
    const int lane = tid & 31;
    const int g    = lane >> 2;       // 0..7
    const int c    = lane & 3;        // 0..3
    const int kb0  = blockIdx.y * KRANGE;
    const int prow0 = blockIdx.y * (KRANGE / 8);
    const int wbcta = blockIdx.x * CTACOLS;

    const uint32_t ws_base = (uint32_t)__cvta_generic_to_shared(ws);

    // chunk = 8 packed rows x 512 B for this CTA's 128 columns (= 4 k-blocks)
    #define ISSUE_CHUNK(ch_)                                                      \
        do {                                                                      \
            const int ch__ = (ch_);                                               \
            if (ch__ < NCHUNKS) {                                                 \
                _Pragma("unroll")                                                 \
                for (int ps = 0; ps < 2; ++ps) {                                  \
                    const int idx  = tid + ps * TPB;                              \
                    const int row  = idx >> 5;                                    \
                    const int col4 = (idx & 31) * 4;                              \
                    const int* gp  = wp + (size_t)(prow0 + ch__ * 8 + row) * NN   \
                                        + wbcta + col4;                           \
                    const uint32_t sa = ws_base +                                 \
                        (uint32_t)((((ch__ & 3) << 10) + (row << 7) + col4) * 4); \
                    asm volatile("cp.async.cg.shared.global [%0], [%1], 16;"      \
                                 :: "r"(sa), "l"(gp));                            \
                }                                                                 \
            }                                                                     \
            asm volatile("cp.async.commit_group;" ::: "memory");                  \
        } while (0)

    // prologue: get 3 chunks in flight BEFORE staging x (overlap both streams)
    ISSUE_CHUNK(0);
    ISSUE_CHUNK(1);
    ISSUE_CHUNK(2);

    // ---- stage x slice [16 x 512] as fp16, k-PERMUTED per 8-k sub-block:
    // position 2j holds k=j, position 2j+1 holds k=j+4  (j = 0..3)
    #pragma unroll
    for (int it = 0; it < 8; ++it) {
        const int p  = tid + it * TPB;        // 8-float chunk id 0..1023
        const int m  = p >> 6;                // 64 chunks per row
        const int k8 = (p & 63) << 3;
        const float4 va = *(const float4*)&x[(size_t)m * KK + kb0 + k8];
        const float4 vb = *(const float4*)&x[(size_t)m * KK + kb0 + k8 + 4];
        *(__half2*)&xs[m][k8]     = __floats2half2_rn(va.x, vb.x);
        *(__half2*)&xs[m][k8 + 2] = __floats2half2_rn(va.y, vb.y);
        *(__half2*)&xs[m][k8 + 4] = __floats2half2_rn(va.z, vb.z);
        *(__half2*)&xs[m][k8 + 6] = __floats2half2_rn(va.w, vb.w);
    }

    const int wb = wbcta + wrp * WCOLS;

    float acc[4][4];
    #pragma unroll
    for (int t = 0; t < 4; ++t)
        #pragma unroll
        for (int r = 0; r < 4; ++r) acc[t][r] = 0.0f;

    const uint32_t sh4 = (uint32_t)c * 4u;

    float snext[4];
    #pragma unroll
    for (int t = 0; t < 4; ++t)
        snext[t] = scales[(size_t)(blockIdx.y * NGRP) * NN + wb + t * 8 + g];
    __half2 s2[4];

    // main loop over 8 chunks; scale group = 2 chunks
    #pragma unroll 1
    for (int ch = 0; ch < NCHUNKS; ++ch) {
        asm volatile("cp.async.wait_group 2;" ::: "memory");
        __syncthreads();                 // chunk ch visible to all; ring slot reusable
        ISSUE_CHUNK(ch + 3);

        if ((ch & 1) == 0) {             // new scale group every 2 chunks
            #pragma unroll
            for (int t = 0; t < 4; ++t)
                s2[t] = __half2half2(__float2half_rn(0.5f * snext[t]));
            const int gn = ((ch >> 1) + 1 < NGRP) ? (ch >> 1) + 1 : (ch >> 1);
            const size_t grow = (size_t)(blockIdx.y * NGRP + gn) * NN;
            #pragma unroll
            for (int t = 0; t < 4; ++t)
                snext[t] = scales[grow + wb + t * 8 + g];
        }

        const int wsb = (ch & 3) << 10;  // ring-slot word base
        #pragma unroll
        for (int j = 0; j < 4; ++j) {
            const int kb  = ch * 4 + j;
            const int klo = kb * 16 + c * 2;
            const uint32_t a0 = *(const uint32_t*)&xs[g][klo];
            const uint32_t a1 = *(const uint32_t*)&xs[g + 8][klo];
            const uint32_t a2 = *(const uint32_t*)&xs[g][klo + 8];
            const uint32_t a3 = *(const uint32_t*)&xs[g + 8][klo + 8];
            const int rb = wsb + (j << 8) + (wrp << 5) + g;  // row0 base + warp cols
            #pragma unroll
            for (int t = 0; t < 4; ++t) {
                const uint32_t w0 = ws[rb + t * 8];          // row 0 word
                const uint32_t w1 = ws[rb + 128 + t * 8];    // row 1 word
                const __half2 b0 = dq4(w0, sh4, s2[t]);
                const __half2 b1 = dq4(w1, sh4, s2[t]);
                hmma(acc[t], a0, a1, a2, a3,
                     *(const uint32_t*)&b0, *(const uint32_t*)&b1);
            }
        }
    }

    // ---- epilogue: write K-split partials ----
    const size_t pbase = (size_t)blockIdx.y * MM * NN;
    #pragma unroll
    for (int t = 0; t < 4; ++t) {
        const int n = wb + t * 8 + c * 2;
        *(float2*)&g_part[pbase + (size_t)g * NN + n]       = make_float2(acc[t][0], acc[t][1]);
        *(float2*)&g_part[pbase + (size_t)(g + 8) * NN + n] = make_float2(acc[t][2], acc[t][3]);
    }
    #undef ISSUE_CHUNK
}

// ---------------- stage 2: one output per thread, 1024 CTAs for overlap ----------------
__global__ void __launch_bounds__(128)
fp4hmma_reduce(float* __restrict__ out)
{
    const int idx = blockIdx.x * 128 + threadIdx.x;   // m*NN + n, 131072 threads
    float v[KSPLIT];
    #pragma unroll
    for (int i = 0; i < KSPLIT; ++i)
        v[i] = g_part[(size_t)i * MM * NN + idx];     // 16 coalesced loads in flight
    #pragma unroll
    for (int stride = 1; stride < KSPLIT; stride <<= 1)
        #pragma unroll
        for (int i = 0; i < KSPLIT; i += 2 * stride)
            v[i] += v[i + stride];
    out[idx] = __half2float(__float2half(v[0]));
}

extern "C" void kernel_launch(void* const* d_in, const int* in_sizes, int n_in,
                              void* d_out, int out_size)
{
    const float* x      = (const float*)d_in[0];
    const int*   wp     = (const int*)  d_in[1];
    const float* scales = (const float*)d_in[2];
    float*       out    = (float*)d_out;

    dim3 grid(NCTA_N, KSPLIT);
    fp4hmma_stage1<<<grid, TPB>>>(x, wp, scales);
    fp4hmma_reduce<<<(MM * NN) / 128, 128>>>(out);
}